// round 4
// baseline (speedup 1.0000x reference)
#include <cuda_runtime.h>
#include <cuda_bf16.h>
#include <math.h>

// Problem constants
// B=128 batches, 80 nodes (2 frames x 40), channels per layer 256->256->128->64->2
#define NB   128
#define NN   80
#define NFR  40

// Scratch (device globals; no allocations allowed)
#define MAXELEM (128*80*256)
__device__ float g_h1[MAXELEM];
__device__ float g_h2[MAXELEM];
__device__ float g_D [MAXELEM];
__device__ float g_T [MAXELEM];
__device__ float g_A [MAXELEM];
__device__ float g_Bf[MAXELEM];

// ---------------- f32x2 helpers (FFMA2 path) ----------------
__device__ __forceinline__ unsigned long long splat2(float x) {
    unsigned long long r;
    asm("mov.b64 %0, {%1, %1};" : "=l"(r) : "f"(x));
    return r;
}
__device__ __forceinline__ void fma2(unsigned long long& d,
                                     unsigned long long a,
                                     unsigned long long b) {
    asm("fma.rn.f32x2 %0, %1, %2, %0;" : "+l"(d) : "l"(a), "l"(b));
}
__device__ __forceinline__ float2 ull2f2(unsigned long long u) {
    float2 f;
    asm("mov.b64 {%0, %1}, %2;" : "=f"(f.x), "=f"(f.y) : "l"(u));
    return f;
}

// ---------------- Generic tile GEMM: Out[r, n] = sum_k H[hrow(r), k] * W[n, coloff+k] ----------------
// mode 0: hrow = r                       (D GEMM, also the initial x@W0^T GEMM)
// mode 1: hrow = frame-swapped r        (T GEMM, temporal edge W block 40)
// mode 2: per-z weight block l=z+1; 512 rows: first 256 -> A part (m=l-1), next 256 -> B part (m=l)
// Requirements: M multiple of 128, K multiple of 16. N guarded.
__global__ __launch_bounds__(256, 2)
void gemm_kernel(const float* __restrict__ H, const float* __restrict__ W,
                 const float* __restrict__ bias,
                 float* __restrict__ OutA, float* __restrict__ OutB,
                 int M, int N, int K, int ldw, int coloff, int mode)
{
    __shared__ float As[16 * 128];   // [k][m]
    __shared__ float Bs[16 * 128];   // [k][n]

    const int tid = threadIdx.x;
    const int tx  = tid & 15;
    const int ty  = tid >> 4;
    const int m0  = blockIdx.x * 128;
    const int n0  = blockIdx.y * 128;
    int l = 1;
    if (mode == 2) { l = (int)blockIdx.z + 1; coloff = l * K; }

    // loader mapping: each thread loads 8 consecutive k of one row, for both tiles
    const int lr = tid >> 1;          // tile row 0..127
    const int lk = (tid & 1) * 8;     // k offset 0 or 8

    const int gr = m0 + lr;           // global out-row this thread loads for A
    int hrow;
    if (mode == 0) {
        hrow = gr;
    } else if (mode == 1) {
        int b = gr / 80; int n = gr % 80;
        hrow = b * 80 + ((n + 40) % 80);
    } else {
        int part = gr >> 8;           // 0 => A (m=l-1), 1 => B (m=l)
        int bf   = gr & 255;          // b*2+f
        int mm   = part ? l : (l - 1);
        hrow = (bf >> 1) * 80 + (bf & 1) * 40 + mm;
    }
    const float* hp = H + (size_t)hrow * K + lk;
    const int bn = n0 + lr;
    const float* wp = (bn < N) ? (W + (size_t)bn * ldw + coloff + lk) : (const float*)0;

    unsigned long long acc[8][4];
#pragma unroll
    for (int i = 0; i < 8; i++)
#pragma unroll
        for (int j = 0; j < 4; j++) acc[i][j] = 0ull;

    for (int k0 = 0; k0 < K; k0 += 16) {
        float4 a0 = *(const float4*)(hp + k0);
        float4 a1 = *(const float4*)(hp + k0 + 4);
        float4 b0 = make_float4(0.f, 0.f, 0.f, 0.f), b1 = b0;
        if (wp) { b0 = *(const float4*)(wp + k0); b1 = *(const float4*)(wp + k0 + 4); }

        // transposed stores into k-major smem
        As[(lk + 0) * 128 + lr] = a0.x;  As[(lk + 1) * 128 + lr] = a0.y;
        As[(lk + 2) * 128 + lr] = a0.z;  As[(lk + 3) * 128 + lr] = a0.w;
        As[(lk + 4) * 128 + lr] = a1.x;  As[(lk + 5) * 128 + lr] = a1.y;
        As[(lk + 6) * 128 + lr] = a1.z;  As[(lk + 7) * 128 + lr] = a1.w;
        Bs[(lk + 0) * 128 + lr] = b0.x;  Bs[(lk + 1) * 128 + lr] = b0.y;
        Bs[(lk + 2) * 128 + lr] = b0.z;  Bs[(lk + 3) * 128 + lr] = b0.w;
        Bs[(lk + 4) * 128 + lr] = b1.x;  Bs[(lk + 5) * 128 + lr] = b1.y;
        Bs[(lk + 6) * 128 + lr] = b1.z;  Bs[(lk + 7) * 128 + lr] = b1.w;
        __syncthreads();

#pragma unroll
        for (int kk = 0; kk < 16; kk++) {
            const float4 av0 = *(const float4*)&As[kk * 128 + ty * 8];
            const float4 av1 = *(const float4*)&As[kk * 128 + ty * 8 + 4];
            const ulonglong2 bv0 = *(const ulonglong2*)&Bs[kk * 128 + tx * 8];
            const ulonglong2 bv1 = *(const ulonglong2*)&Bs[kk * 128 + tx * 8 + 4];
            unsigned long long bp0 = bv0.x, bp1 = bv0.y, bp2 = bv1.x, bp3 = bv1.y;
            float a[8] = {av0.x, av0.y, av0.z, av0.w, av1.x, av1.y, av1.z, av1.w};
#pragma unroll
            for (int i = 0; i < 8; i++) {
                unsigned long long as2 = splat2(a[i]);
                fma2(acc[i][0], as2, bp0);
                fma2(acc[i][1], as2, bp1);
                fma2(acc[i][2], as2, bp2);
                fma2(acc[i][3], as2, bp3);
            }
        }
        __syncthreads();
    }

    // epilogue
#pragma unroll
    for (int i = 0; i < 8; i++) {
        int r = m0 + ty * 8 + i;
        float* op;
        if (mode == 2) {
            int part = r >> 8; int bf = r & 255;
            int mm = part ? l : (l - 1);
            op = (part ? OutB : OutA) + (size_t)(bf * 40 + mm) * N;
        } else {
            op = OutA + (size_t)r * N;
        }
#pragma unroll
        for (int j = 0; j < 4; j++) {
            int n = n0 + tx * 8 + j * 2;
            float2 v = ull2f2(acc[i][j]);
            if (n < N)     { float o = v.x; if (bias) o += bias[n];     op[n]     = o; }
            if (n + 1 < N) { float o = v.y; if (bias) o += bias[n + 1]; op[n + 1] = o; }
        }
    }
}

// ---------------- Combine: out[b, f*40+j, c] = elu?( bias + D + T + prefixA(<j) + suffixB(>j) ) ----------------
__global__ void combine_kernel(const float* __restrict__ D, const float* __restrict__ T,
                               const float* __restrict__ A, const float* __restrict__ B,
                               const float* __restrict__ bias, float* __restrict__ out,
                               int Cout, int elu)
{
    const int b = blockIdx.x;
    const int f = blockIdx.y;
    const int bf = b * 2 + f;
    for (int c = threadIdx.x; c < Cout; c += blockDim.x) {
        float suf = 0.f;
        for (int m = 1; m < 40; m++)
            suf += B[(size_t)(bf * 40 + m) * Cout + c];
        float pref = 0.f;
        const float bias_c = bias[c];
        for (int j = 0; j < 40; j++) {
            int r = b * 80 + f * 40 + j;
            float v = bias_c + D[(size_t)r * Cout + c] + T[(size_t)r * Cout + c] + pref + suf;
            if (elu) v = (v > 0.f) ? v : expm1f(v);
            out[(size_t)r * Cout + c] = v;
            if (j < 39) {
                pref += A[(size_t)(bf * 40 + j) * Cout + c];
                suf  -= B[(size_t)(bf * 40 + j + 1) * Cout + c];
            }
        }
    }
}

// ---------------- Host-side driver ----------------
static void run_layer(const float* h_in, const float* W, const float* bias,
                      float* h_out, int Cin, int Cout, int elu,
                      float* dD, float* dT, float* dA, float* dB)
{
    const int ldw = Cin * 41;
    const int ny = (Cout + 127) / 128;
    // D : W block 0 applied to all 10240 rows
    gemm_kernel<<<dim3(NB * NN / 128, ny), 256>>>(h_in, W, 0, dD, 0,
                                                  NB * NN, Cout, Cin, ldw, 0, 0);
    // T : W block 40 applied to frame-swapped rows
    gemm_kernel<<<dim3(NB * NN / 128, ny), 256>>>(h_in, W, 0, dT, 0,
                                                  NB * NN, Cout, Cin, ldw, 40 * Cin, 1);
    // A/B : W block l (l=1..39), 512 rows each (256 A-part + 256 B-part)
    gemm_kernel<<<dim3(512 / 128, ny, 39), 256>>>(h_in, W, 0, dA, dB,
                                                  512, Cout, Cin, ldw, 0, 2);
    // prefix/suffix combine + bias (+ ELU)
    combine_kernel<<<dim3(NB, 2), 256>>>(dD, dT, dA, dB, bias, h_out, Cout, elu);
}

extern "C" void kernel_launch(void* const* d_in, const int* in_sizes, int n_in,
                              void* d_out, int out_size)
{
    const float* x  = (const float*)d_in[0];
    const float* W0 = (const float*)d_in[1];
    const float* b0 = (const float*)d_in[2];
    const float* W1 = (const float*)d_in[3];
    const float* b1 = (const float*)d_in[4];
    const float* W2 = (const float*)d_in[5];
    const float* b2 = (const float*)d_in[6];
    const float* W3 = (const float*)d_in[7];
    const float* b3 = (const float*)d_in[8];
    const float* W4 = (const float*)d_in[9];
    const float* b4 = (const float*)d_in[10];
    float* out = (float*)d_out;

    float *h1, *h2, *dD, *dT, *dA, *dB;
    cudaGetSymbolAddress((void**)&h1, g_h1);
    cudaGetSymbolAddress((void**)&h2, g_h2);
    cudaGetSymbolAddress((void**)&dD, g_D);
    cudaGetSymbolAddress((void**)&dT, g_T);
    cudaGetSymbolAddress((void**)&dA, g_A);
    cudaGetSymbolAddress((void**)&dB, g_Bf);

    // Initial GEMM: h1[b, o] = x[b,:] . W0[o,:] + b0[o]   (M=128, N=20480, K=1024)
    gemm_kernel<<<dim3(1, 160), 256>>>(x, W0, b0, h1, 0, NB, NN * 256, 1024, 1024, 0, 0);

    // SpiralConv stack
    run_layer(h1, W1, b1, h2, 256, 256, 1, dD, dT, dA, dB);   // 256 -> 256, ELU
    run_layer(h2, W2, b2, h1, 256, 128, 1, dD, dT, dA, dB);   // 256 -> 128, ELU
    run_layer(h1, W3, b3, h2, 128,  64, 1, dD, dT, dA, dB);   // 128 ->  64, ELU
    run_layer(h2, W4, b4, out,  64,   2, 0, dD, dT, dA, dB);  //  64 ->   2, no ELU
}

// round 5
// speedup vs baseline: 1.3390x; 1.3390x over previous
#include <cuda_runtime.h>
#include <cuda_bf16.h>
#include <math.h>

// B=128 batches, 80 nodes (2 frames x 40), channels 256->256->128->64->2
#define NB   128
#define NN   80

#define MAXELEM (128*80*256)
__device__ float g_h1[MAXELEM];
__device__ float g_h2[MAXELEM];
__device__ float g_D [MAXELEM];
__device__ float g_T [MAXELEM];
__device__ float g_A [MAXELEM];
__device__ float g_Bf[MAXELEM];

// ---------------- f32x2 helpers (FFMA2 path) ----------------
__device__ __forceinline__ unsigned long long splat2(float x) {
    unsigned long long r;
    asm("mov.b64 %0, {%1, %1};" : "=l"(r) : "f"(x));
    return r;
}
__device__ __forceinline__ void fma2(unsigned long long& d,
                                     unsigned long long a,
                                     unsigned long long b) {
    asm("fma.rn.f32x2 %0, %1, %2, %0;" : "+l"(d) : "l"(a), "l"(b));
}
__device__ __forceinline__ float2 ull2f2(unsigned long long u) {
    float2 f;
    asm("mov.b64 {%0, %1}, %2;" : "=f"(f.x), "=f"(f.y) : "l"(u));
    return f;
}

// ---------------- Fused tile GEMM ----------------
// One launch covers all three GEMM families of a layer via blockIdx.x decode:
//   bx < tilesD            : mode 0 (D)  hrow = r,                weight block 0
//   bx < 2*tilesD          : mode 1 (T)  hrow = frame-swapped r,  weight block 40
//   else                   : mode 2 (A/B) idx = bx-2*tilesD, l = idx/4+1, mtile = idx%4
//                            512 rows: first 256 -> A (m=l-1), next 256 -> B (m=l)
// Also used for the initial x@W0^T GEMM (tilesD=1, grid.x=1 => mode 0, bias!=null).
// Out[r,n] = sum_k H[hrow(r), k] * W[n, coloff + k]   (K multiple of 16; N guarded)
__global__ __launch_bounds__(256, 2)
void gemm_fused(const float* __restrict__ H, const float* __restrict__ W,
                const float* __restrict__ bias,
                float* __restrict__ OutD, float* __restrict__ OutT,
                float* __restrict__ OutA, float* __restrict__ OutB,
                int N, int K, int ldw, int tilesD)
{
    __shared__ float As[2][16 * 128];   // [buf][k][m]
    __shared__ float Bs[2][16 * 128];   // [buf][k][n]

    const int tid = threadIdx.x;
    const int tx  = tid & 15;
    const int ty  = tid >> 4;
    const int n0  = blockIdx.y * 128;

    // decode mode / m-tile
    int bx = blockIdx.x;
    int mode, m0, l = 0, coloff;
    if (bx < tilesD)            { mode = 0; m0 = bx * 128;            coloff = 0; }
    else if (bx < 2 * tilesD)   { mode = 1; m0 = (bx - tilesD) * 128; coloff = 40 * K; }
    else { mode = 2; int idx = bx - 2 * tilesD; l = idx / 4 + 1; m0 = (idx & 3) * 128; coloff = l * K; }

    // loader mapping: thread loads 8 consecutive k of one tile-row, both tiles
    const int lr = tid >> 1;          // tile row 0..127
    const int lk = (tid & 1) * 8;     // k offset 0 or 8

    const int gr = m0 + lr;
    int hrow;
    if (mode == 0) {
        hrow = gr;
    } else if (mode == 1) {
        int b = gr / 80; int n = gr % 80;
        hrow = b * 80 + ((n + 40) % 80);
    } else {
        int part = gr >> 8;           // 0 => A (m=l-1), 1 => B (m=l)
        int bf   = gr & 255;          // b*2+f
        int mm   = part ? l : (l - 1);
        hrow = (bf >> 1) * 80 + (bf & 1) * 40 + mm;
    }
    const float* hp = H + (size_t)hrow * K + lk;
    const int bn = n0 + lr;
    const float* wp = (bn < N) ? (W + (size_t)bn * ldw + coloff + lk) : (const float*)0;

    unsigned long long acc[8][4];
#pragma unroll
    for (int i = 0; i < 8; i++)
#pragma unroll
        for (int j = 0; j < 4; j++) acc[i][j] = 0ull;

    const int T = K >> 4;

    // ---- preload tile 0 ----
    float4 pa0 = *(const float4*)(hp);
    float4 pa1 = *(const float4*)(hp + 4);
    float4 pb0 = make_float4(0.f, 0.f, 0.f, 0.f), pb1 = pb0;
    if (wp) { pb0 = *(const float4*)(wp); pb1 = *(const float4*)(wp + 4); }
    {
        float* as = &As[0][0]; float* bs = &Bs[0][0];
        as[(lk+0)*128+lr]=pa0.x; as[(lk+1)*128+lr]=pa0.y; as[(lk+2)*128+lr]=pa0.z; as[(lk+3)*128+lr]=pa0.w;
        as[(lk+4)*128+lr]=pa1.x; as[(lk+5)*128+lr]=pa1.y; as[(lk+6)*128+lr]=pa1.z; as[(lk+7)*128+lr]=pa1.w;
        bs[(lk+0)*128+lr]=pb0.x; bs[(lk+1)*128+lr]=pb0.y; bs[(lk+2)*128+lr]=pb0.z; bs[(lk+3)*128+lr]=pb0.w;
        bs[(lk+4)*128+lr]=pb1.x; bs[(lk+5)*128+lr]=pb1.y; bs[(lk+6)*128+lr]=pb1.z; bs[(lk+7)*128+lr]=pb1.w;
    }

    int buf = 0;
    for (int t = 0; t < T; ++t) {
        const bool nx = (t + 1 < T);
        // prefetch next k-tile into registers (LDG issued before the barrier)
        if (nx) {
            const int ko = (t + 1) << 4;
            pa0 = *(const float4*)(hp + ko);
            pa1 = *(const float4*)(hp + ko + 4);
            if (wp) { pb0 = *(const float4*)(wp + ko); pb1 = *(const float4*)(wp + ko + 4); }
        }
        __syncthreads();   // smem[buf] stores (prev iter) complete

        // ---- compute on smem[buf] ----
        const float* asb = &As[buf][0];
        const float* bsb = &Bs[buf][0];
#pragma unroll
        for (int kk = 0; kk < 16; kk++) {
            const float4 av0 = *(const float4*)(asb + kk * 128 + ty * 8);
            const float4 av1 = *(const float4*)(asb + kk * 128 + ty * 8 + 4);
            const ulonglong2 bv0 = *(const ulonglong2*)(bsb + kk * 128 + tx * 8);
            const ulonglong2 bv1 = *(const ulonglong2*)(bsb + kk * 128 + tx * 8 + 4);
            const unsigned long long bp0 = bv0.x, bp1 = bv0.y, bp2 = bv1.x, bp3 = bv1.y;
            float a[8] = {av0.x, av0.y, av0.z, av0.w, av1.x, av1.y, av1.z, av1.w};
#pragma unroll
            for (int i = 0; i < 8; i++) {
                unsigned long long as2 = splat2(a[i]);
                fma2(acc[i][0], as2, bp0);
                fma2(acc[i][1], as2, bp1);
                fma2(acc[i][2], as2, bp2);
                fma2(acc[i][3], as2, bp3);
            }
        }

        // ---- store next tile into the other buffer ----
        if (nx) {
            float* as = &As[buf ^ 1][0]; float* bs = &Bs[buf ^ 1][0];
            as[(lk+0)*128+lr]=pa0.x; as[(lk+1)*128+lr]=pa0.y; as[(lk+2)*128+lr]=pa0.z; as[(lk+3)*128+lr]=pa0.w;
            as[(lk+4)*128+lr]=pa1.x; as[(lk+5)*128+lr]=pa1.y; as[(lk+6)*128+lr]=pa1.z; as[(lk+7)*128+lr]=pa1.w;
            bs[(lk+0)*128+lr]=pb0.x; bs[(lk+1)*128+lr]=pb0.y; bs[(lk+2)*128+lr]=pb0.z; bs[(lk+3)*128+lr]=pb0.w;
            bs[(lk+4)*128+lr]=pb1.x; bs[(lk+5)*128+lr]=pb1.y; bs[(lk+6)*128+lr]=pb1.z; bs[(lk+7)*128+lr]=pb1.w;
            buf ^= 1;
        }
    }

    // ---- epilogue ----
#pragma unroll
    for (int i = 0; i < 8; i++) {
        int r = m0 + ty * 8 + i;
        float* op;
        if (mode == 2) {
            int part = r >> 8; int bf = r & 255;
            int mm = part ? l : (l - 1);
            op = (part ? OutB : OutA) + (size_t)(bf * 40 + mm) * N;
        } else {
            op = (mode ? OutT : OutD) + (size_t)r * N;
        }
#pragma unroll
        for (int j = 0; j < 4; j++) {
            int n = n0 + tx * 8 + j * 2;
            float2 v = ull2f2(acc[i][j]);
            if (n < N)     { float o = v.x; if (bias) o += bias[n];     op[n]     = o; }
            if (n + 1 < N) { float o = v.y; if (bias) o += bias[n + 1]; op[n + 1] = o; }
        }
    }
}

// ---------------- Combine: out[b, f*40+j, c] = elu?( bias + D + T + prefixA(<j) + suffixB(>j) ) --------
__global__ void combine_kernel(const float* __restrict__ D, const float* __restrict__ T,
                               const float* __restrict__ A, const float* __restrict__ B,
                               const float* __restrict__ bias, float* __restrict__ out,
                               int Cout, int elu)
{
    const int b = blockIdx.x;
    const int f = blockIdx.y;
    const int bf = b * 2 + f;
    for (int c = threadIdx.x; c < Cout; c += blockDim.x) {
        float suf = 0.f;
        for (int m = 1; m < 40; m++)
            suf += B[(size_t)(bf * 40 + m) * Cout + c];
        float pref = 0.f;
        const float bias_c = bias[c];
        for (int j = 0; j < 40; j++) {
            int r = b * 80 + f * 40 + j;
            float v = bias_c + D[(size_t)r * Cout + c] + T[(size_t)r * Cout + c] + pref + suf;
            if (elu) v = (v > 0.f) ? v : expm1f(v);
            out[(size_t)r * Cout + c] = v;
            if (j < 39) {
                pref += A[(size_t)(bf * 40 + j) * Cout + c];
                suf  -= B[(size_t)(bf * 40 + j + 1) * Cout + c];
            }
        }
    }
}

// ---------------- Host-side driver ----------------
static void run_layer(const float* h_in, const float* W, const float* bias,
                      float* h_out, int Cin, int Cout, int elu,
                      float* dD, float* dT, float* dA, float* dB)
{
    const int ldw = Cin * 41;
    const int ny = (Cout + 127) / 128;
    const int tilesD = NB * NN / 128;                 // 80
    const int gx = 2 * tilesD + 39 * 4;               // 316: D + T + A/B tiles
    gemm_fused<<<dim3(gx, ny), 256>>>(h_in, W, 0, dD, dT, dA, dB,
                                      Cout, Cin, ldw, tilesD);
    combine_kernel<<<dim3(NB, 2), 256>>>(dD, dT, dA, dB, bias, h_out, Cout, elu);
}

extern "C" void kernel_launch(void* const* d_in, const int* in_sizes, int n_in,
                              void* d_out, int out_size)
{
    const float* x  = (const float*)d_in[0];
    const float* W0 = (const float*)d_in[1];
    const float* b0 = (const float*)d_in[2];
    const float* W1 = (const float*)d_in[3];
    const float* b1 = (const float*)d_in[4];
    const float* W2 = (const float*)d_in[5];
    const float* b2 = (const float*)d_in[6];
    const float* W3 = (const float*)d_in[7];
    const float* b3 = (const float*)d_in[8];
    const float* W4 = (const float*)d_in[9];
    const float* b4 = (const float*)d_in[10];
    float* out = (float*)d_out;

    float *h1, *h2, *dD, *dT, *dA, *dB;
    cudaGetSymbolAddress((void**)&h1, g_h1);
    cudaGetSymbolAddress((void**)&h2, g_h2);
    cudaGetSymbolAddress((void**)&dD, g_D);
    cudaGetSymbolAddress((void**)&dT, g_T);
    cudaGetSymbolAddress((void**)&dA, g_A);
    cudaGetSymbolAddress((void**)&dB, g_Bf);

    // Initial GEMM: h1[b, o] = x[b,:] . W0[o,:] + b0[o]   (M=128, N=20480, K=1024)
    gemm_fused<<<dim3(1, 160), 256>>>(x, W0, b0, h1, h1, h1, h1,
                                      NN * 256, 1024, 1024, 1);

    // SpiralConv stack
    run_layer(h1, W1, b1, h2, 256, 256, 1, dD, dT, dA, dB);   // 256 -> 256, ELU
    run_layer(h2, W2, b2, h1, 256, 128, 1, dD, dT, dA, dB);   // 256 -> 128, ELU
    run_layer(h1, W3, b3, h2, 128,  64, 1, dD, dT, dA, dB);   // 128 ->  64, ELU
    run_layer(h2, W4, b4, out,  64,   2, 0, dD, dT, dA, dB);  //  64 ->   2, no ELU
}

// round 6
// speedup vs baseline: 1.5222x; 1.1368x over previous
#include <cuda_runtime.h>
#include <cuda_bf16.h>
#include <math.h>

// B=128 batches, 80 nodes (2 frames x 40), channels 256->256->128->64->2
#define NB   128
#define NN   80

#define MAXELEM (128*80*256)
__device__ float g_h1[MAXELEM];
__device__ float g_h2[MAXELEM];
__device__ float g_D [MAXELEM];
__device__ float g_T [MAXELEM];
__device__ float g_A [MAXELEM];
__device__ float g_Bf[MAXELEM];

// ---------------- f32x2 helpers (FFMA2 path) ----------------
__device__ __forceinline__ unsigned long long splat2(float x) {
    unsigned long long r;
    asm("mov.b64 %0, {%1, %1};" : "=l"(r) : "f"(x));
    return r;
}
__device__ __forceinline__ void fma2(unsigned long long& d,
                                     unsigned long long a,
                                     unsigned long long b) {
    asm("fma.rn.f32x2 %0, %1, %2, %0;" : "+l"(d) : "l"(a), "l"(b));
}
__device__ __forceinline__ float2 ull2f2(unsigned long long u) {
    float2 f;
    asm("mov.b64 {%0, %1}, %2;" : "=f"(f.x), "=f"(f.y) : "l"(u));
    return f;
}

// ---------------- Fused tile GEMM ----------------
// tilesD > 0 : one launch covers D / T / A-B of a layer via blockIdx.x decode:
//   bx < tilesD          : mode 0 (D)  hrow = r,               W block 0
//   bx < 2*tilesD        : mode 1 (T)  hrow = frame-swapped r, W block 40
//   else                 : mode 2 (A/B) idx=bx-2*tilesD, l=idx/4+1, mtile=idx%4
//                          512 rows: first 256 -> A (m=l-1), next 256 -> B (m=l)
// tilesD == 0 : split-K GEMM for the initial x@W0^T (mode 3):
//   bx = split index p (0/1); K = half-K; both H and W advance by p*K;
//   partial p=0 -> OutD, p=1 -> OutT (reduced+bias later).
// Out[r,n] = sum_k H[hrow(r), k] * W[n, coloff + k]   (K mult of 16; N guarded)
__global__ __launch_bounds__(256, 2)
void gemm_fused(const float* __restrict__ H, const float* __restrict__ W,
                float* __restrict__ OutD, float* __restrict__ OutT,
                float* __restrict__ OutA, float* __restrict__ OutB,
                int N, int K, int ldh, int ldw, int tilesD)
{
    __shared__ float As[2][16 * 128];   // [buf][k][m]
    __shared__ float Bs[2][16 * 128];   // [buf][k][n]

    const int tid = threadIdx.x;
    const int tx  = tid & 15;
    const int ty  = tid >> 4;
    const int n0  = blockIdx.y * 128;

    // decode mode / m-tile
    int bx = blockIdx.x;
    int mode, m0, l = 0, coloffW, coloffH = 0;
    if (tilesD == 0)            { mode = 3; m0 = 0; coloffW = bx * K; coloffH = bx * K; }
    else if (bx < tilesD)       { mode = 0; m0 = bx * 128;            coloffW = 0; }
    else if (bx < 2 * tilesD)   { mode = 1; m0 = (bx - tilesD) * 128; coloffW = 40 * K; }
    else { mode = 2; int idx = bx - 2 * tilesD; l = idx / 4 + 1; m0 = (idx & 3) * 128; coloffW = l * K; }

    // loader mapping: thread loads 8 consecutive k of one tile-row, both tiles
    const int lr = tid >> 1;          // tile row 0..127
    const int lk = (tid & 1) * 8;     // k offset 0 or 8

    const int gr = m0 + lr;
    int hrow;
    if (mode == 0 || mode == 3) {
        hrow = gr;
    } else if (mode == 1) {
        int b = gr / 80; int n = gr % 80;
        hrow = b * 80 + ((n + 40) % 80);
    } else {
        int part = gr >> 8;           // 0 => A (m=l-1), 1 => B (m=l)
        int bf   = gr & 255;          // b*2+f
        int mm   = part ? l : (l - 1);
        hrow = (bf >> 1) * 80 + (bf & 1) * 40 + mm;
    }
    const float* hp = H + (size_t)hrow * ldh + coloffH + lk;
    const int bn = n0 + lr;
    const float* wp = (bn < N) ? (W + (size_t)bn * ldw + coloffW + lk) : (const float*)0;

    unsigned long long acc[8][4];
#pragma unroll
    for (int i = 0; i < 8; i++)
#pragma unroll
        for (int j = 0; j < 4; j++) acc[i][j] = 0ull;

    const int T = K >> 4;

    // ---- preload tile 0 ----
    float4 pa0 = *(const float4*)(hp);
    float4 pa1 = *(const float4*)(hp + 4);
    float4 pb0 = make_float4(0.f, 0.f, 0.f, 0.f), pb1 = pb0;
    if (wp) { pb0 = *(const float4*)(wp); pb1 = *(const float4*)(wp + 4); }
    {
        float* as = &As[0][0]; float* bs = &Bs[0][0];
        as[(lk+0)*128+lr]=pa0.x; as[(lk+1)*128+lr]=pa0.y; as[(lk+2)*128+lr]=pa0.z; as[(lk+3)*128+lr]=pa0.w;
        as[(lk+4)*128+lr]=pa1.x; as[(lk+5)*128+lr]=pa1.y; as[(lk+6)*128+lr]=pa1.z; as[(lk+7)*128+lr]=pa1.w;
        bs[(lk+0)*128+lr]=pb0.x; bs[(lk+1)*128+lr]=pb0.y; bs[(lk+2)*128+lr]=pb0.z; bs[(lk+3)*128+lr]=pb0.w;
        bs[(lk+4)*128+lr]=pb1.x; bs[(lk+5)*128+lr]=pb1.y; bs[(lk+6)*128+lr]=pb1.z; bs[(lk+7)*128+lr]=pb1.w;
    }

    int buf = 0;
    for (int t = 0; t < T; ++t) {
        const bool nx = (t + 1 < T);
        if (nx) {    // prefetch next k-tile into registers
            const int ko = (t + 1) << 4;
            pa0 = *(const float4*)(hp + ko);
            pa1 = *(const float4*)(hp + ko + 4);
            if (wp) { pb0 = *(const float4*)(wp + ko); pb1 = *(const float4*)(wp + ko + 4); }
        }
        __syncthreads();

        const float* asb = &As[buf][0];
        const float* bsb = &Bs[buf][0];
#pragma unroll
        for (int kk = 0; kk < 16; kk++) {
            const float4 av0 = *(const float4*)(asb + kk * 128 + ty * 8);
            const float4 av1 = *(const float4*)(asb + kk * 128 + ty * 8 + 4);
            const ulonglong2 bv0 = *(const ulonglong2*)(bsb + kk * 128 + tx * 8);
            const ulonglong2 bv1 = *(const ulonglong2*)(bsb + kk * 128 + tx * 8 + 4);
            const unsigned long long bp0 = bv0.x, bp1 = bv0.y, bp2 = bv1.x, bp3 = bv1.y;
            float a[8] = {av0.x, av0.y, av0.z, av0.w, av1.x, av1.y, av1.z, av1.w};
#pragma unroll
            for (int i = 0; i < 8; i++) {
                unsigned long long as2 = splat2(a[i]);
                fma2(acc[i][0], as2, bp0);
                fma2(acc[i][1], as2, bp1);
                fma2(acc[i][2], as2, bp2);
                fma2(acc[i][3], as2, bp3);
            }
        }

        if (nx) {
            float* as = &As[buf ^ 1][0]; float* bs = &Bs[buf ^ 1][0];
            as[(lk+0)*128+lr]=pa0.x; as[(lk+1)*128+lr]=pa0.y; as[(lk+2)*128+lr]=pa0.z; as[(lk+3)*128+lr]=pa0.w;
            as[(lk+4)*128+lr]=pa1.x; as[(lk+5)*128+lr]=pa1.y; as[(lk+6)*128+lr]=pa1.z; as[(lk+7)*128+lr]=pa1.w;
            bs[(lk+0)*128+lr]=pb0.x; bs[(lk+1)*128+lr]=pb0.y; bs[(lk+2)*128+lr]=pb0.z; bs[(lk+3)*128+lr]=pb0.w;
            bs[(lk+4)*128+lr]=pb1.x; bs[(lk+5)*128+lr]=pb1.y; bs[(lk+6)*128+lr]=pb1.z; bs[(lk+7)*128+lr]=pb1.w;
            buf ^= 1;
        }
    }

    // ---- epilogue ----
#pragma unroll
    for (int i = 0; i < 8; i++) {
        int r = m0 + ty * 8 + i;
        float* op;
        if (mode == 2) {
            int part = r >> 8; int bf = r & 255;
            int mm = part ? l : (l - 1);
            op = (part ? OutB : OutA) + (size_t)(bf * 40 + mm) * N;
        } else if (mode == 3) {
            op = (bx ? OutT : OutD) + (size_t)r * N;
        } else {
            op = (mode ? OutT : OutD) + (size_t)r * N;
        }
#pragma unroll
        for (int j = 0; j < 4; j++) {
            int n = n0 + tx * 8 + j * 2;
            float2 v = ull2f2(acc[i][j]);
            if (n < N)     op[n]     = v.x;
            if (n + 1 < N) op[n + 1] = v.y;
        }
    }
}

// ---------------- reduce for split-K gemm0: h1 = P0 + P1 + bias ----------------
// N = 20480 columns, 128 rows. Vectorized float4.
__global__ void reduce0_kernel(const float* __restrict__ P0, const float* __restrict__ P1,
                               const float* __restrict__ bias, float* __restrict__ out)
{
    const int i = blockIdx.x * blockDim.x + threadIdx.x;   // float4 index
    const int n4 = 20480 / 4;
    const float4 a = ((const float4*)P0)[i];
    const float4 b = ((const float4*)P1)[i];
    const float4 c = ((const float4*)bias)[i % n4];
    float4 o;
    o.x = a.x + b.x + c.x; o.y = a.y + b.y + c.y;
    o.z = a.z + b.z + c.z; o.w = a.w + b.w + c.w;
    ((float4*)out)[i] = o;
}

// ---------------- Combine v2: smem-staged A/B + 4-way j parallel scan ------------
// grid (bf=256, Cout/64), block 256. out[b,f*40+j,c] = elu( bias + D + T + prefA(<j) + sufB(>j) )
__global__ void combine2_kernel(const float* __restrict__ D, const float* __restrict__ T,
                                const float* __restrict__ A, const float* __restrict__ B,
                                const float* __restrict__ bias, float* __restrict__ out,
                                int Cout)
{
    __shared__ float As[40 * 64];
    __shared__ float Bs[40 * 64];
    const int bf = blockIdx.x;
    const int c0 = blockIdx.y * 64;
    const int tid = threadIdx.x;

    // stage A/B chunk [40][64] (coalesced in c)
    for (int t = tid; t < 40 * 64; t += 256) {
        int j = t >> 6, c = t & 63;
        size_t src = (size_t)(bf * 40 + j) * Cout + c0 + c;
        As[t] = A[src];
        Bs[t] = B[src];
    }
    __syncthreads();

    const int cc = tid & 63;
    const int jg = tid >> 6;          // j-group 0..3, each covers 10 j's
    const int j0 = jg * 10;

    float pref = 0.f, suf = 0.f;
    for (int m = 0; m < j0; m++)      pref += As[m * 64 + cc];
    for (int m = j0 + 1; m < 40; m++) suf  += Bs[m * 64 + cc];

    const int b = bf >> 1, f = bf & 1;
    const float bias_c = bias[c0 + cc];
    const size_t rbase = (size_t)(b * 80 + f * 40) * Cout + c0 + cc;
#pragma unroll
    for (int j = j0; j < j0 + 10; j++) {
        size_t r = rbase + (size_t)j * Cout;
        float v = bias_c + D[r] + T[r] + pref + suf;
        v = (v > 0.f) ? v : expm1f(v);
        out[r] = v;
        if (j < 39) {
            pref += As[j * 64 + cc];
            suf  -= Bs[(j + 1) * 64 + cc];
        }
    }
}

// ---------------- Layer 4 direct: Cout=2, Cin=64, spiral evaluated in-kernel ----
// One block per batch. h (80x64) and W4 (2x2624) staged in smem; warp per node.
__global__ __launch_bounds__(256)
void spiral_small_kernel(const float* __restrict__ Hin, const float* __restrict__ W4,
                         const float* __restrict__ b4, float* __restrict__ out)
{
    __shared__ float hs[80 * 64];      // 20 KB
    __shared__ float ws[2 * 41 * 64];  // 21 KB
    const int b = blockIdx.x;
    const int tid = threadIdx.x;
    const int wid = tid >> 5;
    const int lane = tid & 31;

    const float* hsrc = Hin + (size_t)b * 80 * 64;
    for (int t = tid; t < 80 * 64; t += 256) hs[t] = hsrc[t];
    for (int t = tid; t < 2 * 41 * 64; t += 256) ws[t] = W4[t];
    __syncthreads();

    for (int j = wid; j < 80; j += 8) {
        const int f  = (j >= 40) ? 40 : 0;
        const int jj = j - f;
        const int tnode = (j < 40) ? j + 40 : j - 40;
#pragma unroll
        for (int c = 0; c < 2; c++) {
            const float* w = ws + c * (41 * 64);
            float sum = 0.f;
            for (int idx = lane; idx < 41 * 64; idx += 32) {
                int p = idx >> 6, k = idx & 63;
                int node;
                if (p == 0)       node = j;
                else if (p <= 39) node = f + ((p - 1 < jj) ? p - 1 : p);
                else              node = tnode;
                sum += w[idx] * hs[node * 64 + k];
            }
#pragma unroll
            for (int o = 16; o > 0; o >>= 1)
                sum += __shfl_xor_sync(0xFFFFFFFFu, sum, o);
            if (lane == 0)
                out[(size_t)(b * 80 + j) * 2 + c] = sum + b4[c];
        }
    }
}

// ---------------- Host-side driver ----------------
static void run_layer(const float* h_in, const float* W, const float* bias,
                      float* h_out, int Cin, int Cout,
                      float* dD, float* dT, float* dA, float* dB)
{
    const int ldw = Cin * 41;
    const int ny = (Cout + 127) / 128;
    const int tilesD = NB * NN / 128;                 // 80
    const int gx = 2 * tilesD + 39 * 4;               // 316
    gemm_fused<<<dim3(gx, ny), 256>>>(h_in, W, dD, dT, dA, dB,
                                      Cout, Cin, Cin, ldw, tilesD);
    combine2_kernel<<<dim3(NB * 2, Cout / 64), 256>>>(dD, dT, dA, dB, bias, h_out, Cout);
}

extern "C" void kernel_launch(void* const* d_in, const int* in_sizes, int n_in,
                              void* d_out, int out_size)
{
    const float* x  = (const float*)d_in[0];
    const float* W0 = (const float*)d_in[1];
    const float* b0 = (const float*)d_in[2];
    const float* W1 = (const float*)d_in[3];
    const float* b1 = (const float*)d_in[4];
    const float* W2 = (const float*)d_in[5];
    const float* b2 = (const float*)d_in[6];
    const float* W3 = (const float*)d_in[7];
    const float* b3 = (const float*)d_in[8];
    const float* W4 = (const float*)d_in[9];
    const float* b4 = (const float*)d_in[10];
    float* out = (float*)d_out;

    float *h1, *h2, *dD, *dT, *dA, *dB;
    cudaGetSymbolAddress((void**)&h1, g_h1);
    cudaGetSymbolAddress((void**)&h2, g_h2);
    cudaGetSymbolAddress((void**)&dD, g_D);
    cudaGetSymbolAddress((void**)&dT, g_T);
    cudaGetSymbolAddress((void**)&dA, g_A);
    cudaGetSymbolAddress((void**)&dB, g_Bf);

    // Initial GEMM, split-K=2: partials into dD/dT, then reduce + bias into h1.
    // (M=128, N=20480, K=1024 -> 2 x K=512; grid (2,160) = 320 CTAs fills the chip)
    gemm_fused<<<dim3(2, 160), 256>>>(x, W0, dD, dT, dA, dB,
                                      NN * 256, 512, 1024, 1024, 0);
    reduce0_kernel<<<(NB * NN * 256 / 4) / 256, 256>>>(dD, dT, b0, h1);

    // SpiralConv stack (layers 1-3 via reduced GEMM + scan-combine)
    run_layer(h1, W1, b1, h2, 256, 256, dD, dT, dA, dB);   // 256 -> 256, ELU
    run_layer(h2, W2, b2, h1, 256, 128, dD, dT, dA, dB);   // 256 -> 128, ELU
    run_layer(h1, W3, b3, h2, 128,  64, dD, dT, dA, dB);   // 128 ->  64, ELU

    // Layer 4 (64 -> 2, no ELU): direct spiral evaluation
    spiral_small_kernel<<<NB, 256>>>(h2, W4, b4, out);
}